// round 13
// baseline (speedup 1.0000x reference)
#include <cuda_runtime.h>

// Problem constants (fixed by the reference generator)
#define NGR   64
#define NPG   96
#define NODES (NGR*NPG)       // 6144
#define HID   64
#define INF   32
#define EF    16
#define DEG   8
#define EDGES (NODES*DEG)     // 49152
#define EPG   (NPG*DEG)       // 768
#define PAIRS (NODES*NPG)     // 589824

// ---------------- scratch (static device globals) ---------------------------
__device__ float g_M1[INF*HID];
__device__ float g_M2[EF*HID];
__device__ float g_bn[HID];
__device__ float g_be[HID];
__device__ float g_WA[INF*HID];
__device__ float g_WB[INF*HID];
__device__ float g_WC[EF*HID];
__device__ float g_biasA[HID];
__device__ float g_biasB[HID];
__device__ float g_biasC[HID];
__device__ float g_vecA[NODES*HID];
__device__ float g_vecBT[NGR*HID*NPG];   // [graph][m][j]  m-major transposed
__device__ float g_Ce[(size_t)EDGES*HID];

// ---------------- K1a: first composition stage (parallel) -------------------
__global__ void prep1_kernel(const float* __restrict__ W_atom, const float* __restrict__ b_atom,
                             const float* __restrict__ W_bond, const float* __restrict__ b_bond,
                             const float* __restrict__ W_node, const float* __restrict__ b_node,
                             const float* __restrict__ W_edge, const float* __restrict__ b_edge)
{
    int i = blockIdx.x * blockDim.x + threadIdx.x;
    if (i < INF*HID) {
        int r = i >> 6, k = i & 63;
        float s = 0.f;
        #pragma unroll 8
        for (int j = 0; j < HID; j++) s = fmaf(W_atom[r*HID+j], W_node[j*HID+k], s);
        g_M1[i] = s;
    } else if (i < INF*HID + EF*HID) {
        int i2 = i - INF*HID;
        int r = i2 >> 6, k = i2 & 63;
        float s = 0.f;
        #pragma unroll 8
        for (int j = 0; j < HID; j++) s = fmaf(W_bond[r*HID+j], W_edge[j*HID+k], s);
        g_M2[i2] = s;
    } else if (i < INF*HID + EF*HID + HID) {
        int k = i - (INF*HID + EF*HID);
        float s = b_node[k];
        #pragma unroll 8
        for (int j = 0; j < HID; j++) s = fmaf(b_atom[j], W_node[j*HID+k], s);
        g_bn[k] = s;
    } else if (i < INF*HID + EF*HID + 2*HID) {
        int k = i - (INF*HID + EF*HID + HID);
        float s = b_edge[k];
        #pragma unroll 8
        for (int j = 0; j < HID; j++) s = fmaf(b_bond[j], W_edge[j*HID+k], s);
        g_be[k] = s;
    }
}

// ---------------- K1b: fold into W1 blocks (parallel) ------------------------
__global__ void prep2_kernel(const float* __restrict__ W1, const float* __restrict__ b1)
{
    int i = blockIdx.x * blockDim.x + threadIdx.x;
    if (i < INF*HID) {
        int r = i >> 6, k = i & 63;
        float s = 0.f;
        #pragma unroll 8
        for (int j = 0; j < HID; j++) s = fmaf(g_M1[r*HID+j], W1[j*HID + k], s);
        g_WA[i] = s;
    } else if (i < 2*INF*HID) {
        int i2 = i - INF*HID;
        int r = i2 >> 6, k = i2 & 63;
        float s = 0.f;
        #pragma unroll 8
        for (int j = 0; j < HID; j++) s = fmaf(g_M1[r*HID+j], W1[(64+j)*HID + k], s);
        g_WB[i2] = s;
    } else if (i < 2*INF*HID + EF*HID) {
        int i2 = i - 2*INF*HID;
        int r = i2 >> 6, k = i2 & 63;
        float s = 0.f;
        #pragma unroll 8
        for (int j = 0; j < HID; j++) s = fmaf(g_M2[r*HID+j], W1[(128+j)*HID + k], s);
        g_WC[i2] = s;
    } else if (i < 2*INF*HID + EF*HID + HID) {
        int k = i - (2*INF*HID + EF*HID);
        float sa = b1[k], sb = 0.f, sc = 0.f;
        #pragma unroll 4
        for (int j = 0; j < HID; j++) {
            sa = fmaf(g_bn[j], W1[j*HID + k], sa);
            sb = fmaf(g_bn[j], W1[(64+j)*HID + k], sb);
            sc = fmaf(g_be[j], W1[(128+j)*HID + k], sc);
        }
        g_biasA[k] = sa;
        g_biasB[k] = sb;
        g_biasC[k] = sc;
    }
}

// ---------------- K2: fused per-node + per-edge layer-1 partials -------------
#define NODE_BLOCKS (NODES/2)
#define EDGE_BLOCKS (EDGES/4)
__global__ void encode_kernel(const float* __restrict__ x, const float* __restrict__ ea)
{
    if (blockIdx.x < NODE_BLOCKS) {
        __shared__ float xr[2][INF];
        int half = threadIdx.x >> 7;
        int t    = threadIdx.x & 127;
        int node = blockIdx.x*2 + half;
        if (t < INF) xr[half][t] = x[node*INF + t];
        __syncthreads();
        int k = t & 63;
        const float* W = (t < 64) ? g_WA : g_WB;
        float s = (t < 64) ? g_biasA[k] : g_biasB[k];
        #pragma unroll
        for (int f = 0; f < INF; f++) s = fmaf(xr[half][f], W[f*HID + k], s);
        if (t < 64) {
            g_vecA[node*HID + k] = s;
        } else {
            int gg = node / NPG, lj = node - gg*NPG;
            g_vecBT[gg*(HID*NPG) + k*NPG + lj] = s;     // transposed store
        }
    } else {
        __shared__ float er[4][EF];
        int b   = blockIdx.x - NODE_BLOCKS;
        int grp = threadIdx.x >> 6;
        int k   = threadIdx.x & 63;
        int e   = b * 4 + grp;
        if (k < EF) er[grp][k] = ea[e*EF + k];
        __syncthreads();
        float s = g_biasC[k];
        #pragma unroll
        for (int f = 0; f < EF; f++) s = fmaf(er[grp][f], g_WC[f*HID + k], s);
        g_Ce[(size_t)e*HID + k] = s;
    }
}

// ---------------- K3: fused pairwise MLP, 1 node/block, 192 thr, 4 blk/SM ----
#define W2PITCH 72

#define FMA4(acc, a, b) \
    acc.x = fmaf(a, b.x, acc.x); \
    acc.y = fmaf(a, b.y, acc.y); \
    acc.z = fmaf(a, b.z, acc.z); \
    acc.w = fmaf(a, b.w, acc.w);

__global__ void __launch_bounds__(192, 4)
pair_kernel(const int* __restrict__ edge_index,
            const float* __restrict__ W2, const float* __restrict__ b2,
            const float* __restrict__ W3, const float* __restrict__ b3,
            float* __restrict__ out)
{
    extern __shared__ float s[];
    float* H0   = s;                         // [64][96]
    float* W2s  = s + 64*96;                 // [64][72]
    float* Au_s = W2s + 64*W2PITCH;          // [64]
    float* W3s  = Au_s + 64;                 // [64]
    float* b2s  = W3s + 64;                  // [64]
    long long* el = (long long*)(b2s + 64);  // [96]
    int* e0s    = (int*)(el + 96);           // [96]
    int* e1s    = e0s + 96;                  // [96]
    int* nms    = e1s + 96;                  // [96]
    int* ecount = nms + 96;                  // [1]

    const int lt  = threadIdx.x;             // 0..191
    const int u   = blockIdx.x;
    const int g   = u / NPG;
    const int lu  = u - g*NPG;

    if (lt == 0) ecount[0] = 0;
    for (int idx = lt; idx < 64*64; idx += 192) {
        int m = idx >> 6, k = idx & 63;
        W2s[m*W2PITCH + k] = W2[idx];
    }
    if (lt < 64) {
        Au_s[lt] = g_vecA[(size_t)u*HID + lt];
        W3s[lt]  = W3[lt];
        b2s[lt]  = b2[lt];
    }
    __syncthreads();

    // gather this node's out-edges
    const int* srcA = edge_index;
    const int* dstA = edge_index + EDGES;
    for (int e = g*EPG + lt; e < (g+1)*EPG; e += 192) {
        if (srcA[e] == u) {
            int p = atomicAdd(ecount, 1);
            if (p < 96) el[p] = ((long long)e << 32) | (unsigned)(dstA[e] - g*NPG);
        }
    }
    __syncthreads();
    const int ec = min(ecount[0], 96);
    if (lt == 0) {      // deterministic order
        for (int a = 1; a < ec; a++) {
            long long v = el[a]; int b = a - 1;
            while (b >= 0 && el[b] > v) { el[b+1] = el[b]; b--; }
            el[b+1] = v;
        }
    }
    __syncthreads();

    // per-column edge-match table (thread lt<96 owns column j = lt)
    if (lt < 96) {
        int e0 = -1, e1 = -1, nm = 0;
        for (int q = 0; q < ec; q++) {
            long long pk = el[q];
            if ((int)(pk & 0xffffffffLL) == lt) {
                int e = (int)(pk >> 32);
                if (nm == 0) e0 = e; else if (nm == 1) e1 = e;
                nm++;
            }
        }
        e0s[lt] = e0;
        e1s[lt] = e1;
        nms[lt] = nm;
    }
    __syncthreads();

    // ---- Phase A: branch-free coalesced build ----
    // 64*24 = 1536 float4 slots / 192 threads = 8 iters; j4 invariant,
    // m advances by 8. Clean columns relu'd; edge columns stored pre-relu.
    const float* vBTg = g_vecBT + (size_t)g*(HID*NPG);
    {
        const int j4 = lt % 24;
        const int m0 = lt / 24;               // 0..7
        const int jb = 4*j4;
        const bool c0 = (nms[jb+0] != 0);
        const bool c1 = (nms[jb+1] != 0);
        const bool c2 = (nms[jb+2] != 0);
        const bool c3 = (nms[jb+3] != 0);
        const float4* vBT4 = (const float4*)vBTg;
        #pragma unroll
        for (int m = m0; m < 64; m += 8) {
            float4 v = vBT4[m*24 + j4];
            float  au = Au_s[m];
            v.x += au; v.y += au; v.z += au; v.w += au;
            v.x = c0 ? v.x : fmaxf(v.x, 0.f);
            v.y = c1 ? v.y : fmaxf(v.y, 0.f);
            v.z = c2 ? v.z : fmaxf(v.z, 0.f);
            v.w = c3 ? v.w : fmaxf(v.w, 0.f);
            *(float4*)(H0 + m*96 + jb) = v;
        }
    }
    __syncthreads();

    // ---- Phase B: owner thread finishes edge-bearing columns from SMEM ----
    if (lt < 96) {
        const int nm = nms[lt];
        if (nm > 0) {
            const int j = lt;
            if (nm <= 2) {
                const float* ce0 = g_Ce + (size_t)e0s[lt]*HID;
                const float* ce1 = (nm == 2) ? (g_Ce + (size_t)e1s[lt]*HID) : 0;
                #pragma unroll 8
                for (int m = 0; m < 64; m++) {
                    float v = H0[m*96 + j] + ce0[m];
                    if (ce1) v += ce1[m];
                    H0[m*96 + j] = fmaxf(v, 0.f);
                }
            } else {
                for (int m = 0; m < 64; m++) {
                    float v = H0[m*96 + j];
                    for (int q = 0; q < ec; q++) {
                        long long pk = el[q];
                        if ((int)(pk & 0xffffffffLL) == j)
                            v += g_Ce[(size_t)((int)(pk >> 32))*HID + m];
                    }
                    H0[m*96 + j] = fmaxf(v, 0.f);
                }
            }
        }
    }
    __syncthreads();

    // ---- GEMM: thread (jt,kt) computes h1[jt*8..+8][kt*4..+4] ----
    const int jt = lt >> 4;      // 0..11
    const int kt = lt & 15;      // 0..15
    float4 acc[8];
    #pragma unroll
    for (int a = 0; a < 8; a++) acc[a] = make_float4(0.f, 0.f, 0.f, 0.f);

    const float* Abase = H0 + jt*8;
    const float* Bbase = W2s + kt*4;
    #pragma unroll 4
    for (int m = 0; m < 64; m++) {
        float4 a0 = *(const float4*)(Abase + m*96);
        float4 a1 = *(const float4*)(Abase + m*96 + 4);
        float4 b0 = *(const float4*)(Bbase + m*W2PITCH);
        FMA4(acc[0], a0.x, b0);
        FMA4(acc[1], a0.y, b0);
        FMA4(acc[2], a0.z, b0);
        FMA4(acc[3], a0.w, b0);
        FMA4(acc[4], a1.x, b0);
        FMA4(acc[5], a1.y, b0);
        FMA4(acc[6], a1.z, b0);
        FMA4(acc[7], a1.w, b0);
    }

    // ---- epilogue: relu(h1+b2)*W3 partial, shuffle-reduce over 16 kt lanes ----
    float po[8];
    {
        float4 bb = *(const float4*)(b2s + kt*4);
        float4 ww = *(const float4*)(W3s + kt*4);
        #pragma unroll
        for (int a = 0; a < 8; a++) {
            float p = 0.f;
            p = fmaf(fmaxf(acc[a].x + bb.x, 0.f), ww.x, p);
            p = fmaf(fmaxf(acc[a].y + bb.y, 0.f), ww.y, p);
            p = fmaf(fmaxf(acc[a].z + bb.z, 0.f), ww.z, p);
            p = fmaf(fmaxf(acc[a].w + bb.w, 0.f), ww.w, p);
            po[a] = p;
        }
    }
    #pragma unroll
    for (int ofs = 8; ofs > 0; ofs >>= 1)
        #pragma unroll
        for (int a = 0; a < 8; a++)
            po[a] += __shfl_xor_sync(0xffffffffu, po[a], ofs, 16);

    if (kt == 0) {
        float bias = b3[0];
        float4 o0 = make_float4(po[0]+bias, po[1]+bias, po[2]+bias, po[3]+bias);
        float4 o1 = make_float4(po[4]+bias, po[5]+bias, po[6]+bias, po[7]+bias);
        float* op = out + (size_t)g*(NPG*NPG) + (size_t)lu*NPG + jt*8;
        *(float4*)op       = o0;
        *(float4*)(op + 4) = o1;
    }
}

// ---------------- launch -----------------------------------------------------
extern "C" void kernel_launch(void* const* d_in, const int* in_sizes, int n_in,
                              void* d_out, int out_size)
{
    const float* x          = (const float*)d_in[0];
    const float* edge_attr  = (const float*)d_in[1];
    const int*   edge_index = (const int*)  d_in[2];

    int w = 6;
    if (n_in >= 6 && in_sizes[5] != 1) w = 5;
    if (n_in == 19) w = 5;
    const float* W_atom = (const float*)d_in[w+0];
    const float* b_atom = (const float*)d_in[w+1];
    const float* W_bond = (const float*)d_in[w+2];
    const float* b_bond = (const float*)d_in[w+3];
    const float* W_node = (const float*)d_in[w+4];
    const float* b_node = (const float*)d_in[w+5];
    const float* W_edge = (const float*)d_in[w+6];
    const float* b_edge = (const float*)d_in[w+7];
    const float* W1     = (const float*)d_in[w+8];
    const float* b1     = (const float*)d_in[w+9];
    const float* W2     = (const float*)d_in[w+10];
    const float* b2     = (const float*)d_in[w+11];
    const float* W3     = (const float*)d_in[w+12];
    const float* b3     = (const float*)d_in[w+13];

    const int smem_bytes = (64*96 + 64*W2PITCH + 3*64) * (int)sizeof(float)
                           + 96*(int)sizeof(long long)
                           + (3*96 + 1) * (int)sizeof(int);
    cudaFuncSetAttribute(pair_kernel, cudaFuncAttributeMaxDynamicSharedMemorySize, smem_bytes);

    const int P1 = INF*HID + EF*HID + 2*HID;            // 3200
    const int P2 = 2*INF*HID + EF*HID + HID;            // 5184
    prep1_kernel<<<(P1 + 255)/256, 256>>>(W_atom, b_atom, W_bond, b_bond,
                                          W_node, b_node, W_edge, b_edge);
    prep2_kernel<<<(P2 + 255)/256, 256>>>(W1, b1);
    encode_kernel<<<NODE_BLOCKS + EDGE_BLOCKS, 256>>>(x, edge_attr);
    pair_kernel<<<NODES, 192, smem_bytes>>>(edge_index, W2, b2, W3, b3, (float*)d_out);
}

// round 15
// speedup vs baseline: 1.7858x; 1.7858x over previous
#include <cuda_runtime.h>
#include <cuda_bf16.h>
#include <cstdint>

// Problem constants (fixed by the reference generator)
#define NGR   64
#define NPG   96
#define NODES (NGR*NPG)       // 6144
#define HID   64
#define INF   32
#define EF    16
#define DEG   8
#define EDGES (NODES*DEG)     // 49152
#define EPG   (NPG*DEG)       // 768

// ---------------- scratch (static device globals) ---------------------------
__device__ float g_M1[INF*HID];
__device__ float g_M2[EF*HID];
__device__ float g_bn[HID];
__device__ float g_be[HID];
__device__ float g_WA[INF*HID];
__device__ float g_WB[INF*HID];
__device__ float g_WC[EF*HID];
__device__ float g_biasA[HID];
__device__ float g_biasB[HID];
__device__ float g_biasC[HID];
__device__ float g_vecA[NODES*HID];
__device__ float g_vecB[NODES*HID];              // [node][m]  (m contiguous)
__device__ float g_Ce[(size_t)EDGES*HID];
// W2 as bf16 hi/lo, 64 rows(m) x 64 cols(k), 128B rows, SW128-swizzled image
__device__ unsigned short g_Bhi[64*64];
__device__ unsigned short g_Blo[64*64];

// ---------------- warp-MMA helpers (base-target PTX, sm_80+) ----------------
__device__ __forceinline__ void ldsm_x4(uint32_t* r, uint32_t addr) {
    asm volatile("ldmatrix.sync.aligned.m8n8.x4.shared.b16 {%0,%1,%2,%3}, [%4];"
                 : "=r"(r[0]), "=r"(r[1]), "=r"(r[2]), "=r"(r[3]) : "r"(addr));
}
__device__ __forceinline__ void ldsm_x2t(uint32_t* r, uint32_t addr) {
    asm volatile("ldmatrix.sync.aligned.m8n8.x2.trans.shared.b16 {%0,%1}, [%2];"
                 : "=r"(r[0]), "=r"(r[1]) : "r"(addr));
}
__device__ __forceinline__ void mma16816(float* d, const uint32_t* a, const uint32_t* b) {
    asm volatile(
        "mma.sync.aligned.m16n8k16.row.col.f32.bf16.bf16.f32 "
        "{%0,%1,%2,%3}, {%4,%5,%6,%7}, {%8,%9}, {%0,%1,%2,%3};"
        : "+f"(d[0]), "+f"(d[1]), "+f"(d[2]), "+f"(d[3])
        : "r"(a[0]), "r"(a[1]), "r"(a[2]), "r"(a[3]), "r"(b[0]), "r"(b[1]));
}
__device__ __forceinline__ uint32_t pack_bf16x2(float lo_elem, float hi_elem) {
    uint32_t r;
    asm("cvt.rn.satfinite.bf16x2.f32 %0, %1, %2;" : "=r"(r) : "f"(hi_elem), "f"(lo_elem));
    return r;   // bits[15:0] = lo_elem, bits[31:16] = hi_elem
}
__device__ __forceinline__ uint32_t sw128(uint32_t off) {
    return off ^ ((off >> 3) & 0x70u);
}

// ---------------- K1a ---------------------------------------------------------
__global__ void prep1_kernel(const float* __restrict__ W_atom, const float* __restrict__ b_atom,
                             const float* __restrict__ W_bond, const float* __restrict__ b_bond,
                             const float* __restrict__ W_node, const float* __restrict__ b_node,
                             const float* __restrict__ W_edge, const float* __restrict__ b_edge)
{
    int i = blockIdx.x * blockDim.x + threadIdx.x;
    if (i < INF*HID) {
        int r = i >> 6, k = i & 63;
        float s = 0.f;
        #pragma unroll 8
        for (int j = 0; j < HID; j++) s = fmaf(W_atom[r*HID+j], W_node[j*HID+k], s);
        g_M1[i] = s;
    } else if (i < INF*HID + EF*HID) {
        int i2 = i - INF*HID;
        int r = i2 >> 6, k = i2 & 63;
        float s = 0.f;
        #pragma unroll 8
        for (int j = 0; j < HID; j++) s = fmaf(W_bond[r*HID+j], W_edge[j*HID+k], s);
        g_M2[i2] = s;
    } else if (i < INF*HID + EF*HID + HID) {
        int k = i - (INF*HID + EF*HID);
        float s = b_node[k];
        #pragma unroll 8
        for (int j = 0; j < HID; j++) s = fmaf(b_atom[j], W_node[j*HID+k], s);
        g_bn[k] = s;
    } else if (i < INF*HID + EF*HID + 2*HID) {
        int k = i - (INF*HID + EF*HID + HID);
        float s = b_edge[k];
        #pragma unroll 8
        for (int j = 0; j < HID; j++) s = fmaf(b_bond[j], W_edge[j*HID+k], s);
        g_be[k] = s;
    }
}

// ---------------- K1b ---------------------------------------------------------
__global__ void prep2_kernel(const float* __restrict__ W1, const float* __restrict__ b1)
{
    int i = blockIdx.x * blockDim.x + threadIdx.x;
    if (i < INF*HID) {
        int r = i >> 6, k = i & 63;
        float s = 0.f;
        #pragma unroll 8
        for (int j = 0; j < HID; j++) s = fmaf(g_M1[r*HID+j], W1[j*HID + k], s);
        g_WA[i] = s;
    } else if (i < 2*INF*HID) {
        int i2 = i - INF*HID;
        int r = i2 >> 6, k = i2 & 63;
        float s = 0.f;
        #pragma unroll 8
        for (int j = 0; j < HID; j++) s = fmaf(g_M1[r*HID+j], W1[(64+j)*HID + k], s);
        g_WB[i2] = s;
    } else if (i < 2*INF*HID + EF*HID) {
        int i2 = i - 2*INF*HID;
        int r = i2 >> 6, k = i2 & 63;
        float s = 0.f;
        #pragma unroll 8
        for (int j = 0; j < HID; j++) s = fmaf(g_M2[r*HID+j], W1[(128+j)*HID + k], s);
        g_WC[i2] = s;
    } else if (i < 2*INF*HID + EF*HID + HID) {
        int k = i - (2*INF*HID + EF*HID);
        float sa = b1[k], sb = 0.f, sc = 0.f;
        #pragma unroll 4
        for (int j = 0; j < HID; j++) {
            sa = fmaf(g_bn[j], W1[j*HID + k], sa);
            sb = fmaf(g_bn[j], W1[(64+j)*HID + k], sb);
            sc = fmaf(g_be[j], W1[(128+j)*HID + k], sc);
        }
        g_biasA[k] = sa;
        g_biasB[k] = sb;
        g_biasC[k] = sc;
    }
}

// ---------------- K1c: W2 -> swizzled bf16 hi/lo global image ----------------
// B[m][k] = W2[m][k] (row-major, k contiguous, 128B rows), SW128-swizzled.
__global__ void prep3_kernel(const float* __restrict__ W2)
{
    int i = blockIdx.x * blockDim.x + threadIdx.x;
    if (i >= 64*64) return;
    int m = i >> 6, k = i & 63;
    float v = W2[m*HID + k];
    uint32_t b  = __float_as_uint(v);
    uint32_t hb = (b + 0x7FFFu + ((b >> 16) & 1u)) & 0xFFFF0000u;
    float hf = __uint_as_float(hb);
    float l  = v - hf;
    uint32_t lb32 = __float_as_uint(l);
    uint32_t lb   = (lb32 + 0x7FFFu + ((lb32 >> 16) & 1u)) & 0xFFFF0000u;
    uint32_t off = (uint32_t)m*128u + (uint32_t)k*2u;
    uint32_t sw  = sw128(off);
    g_Bhi[sw >> 1] = (unsigned short)(hb >> 16);
    g_Blo[sw >> 1] = (unsigned short)(lb >> 16);
}

// ---------------- K2: fused per-node + per-edge layer-1 partials -------------
#define NODE_BLOCKS (NODES/2)
#define EDGE_BLOCKS (EDGES/4)
__global__ void encode_kernel(const float* __restrict__ x, const float* __restrict__ ea)
{
    if (blockIdx.x < NODE_BLOCKS) {
        __shared__ float xr[2][INF];
        int half = threadIdx.x >> 7;
        int t    = threadIdx.x & 127;
        int node = blockIdx.x*2 + half;
        if (t < INF) xr[half][t] = x[node*INF + t];
        __syncthreads();
        int k = t & 63;
        const float* W = (t < 64) ? g_WA : g_WB;
        float s = (t < 64) ? g_biasA[k] : g_biasB[k];
        #pragma unroll
        for (int f = 0; f < INF; f++) s = fmaf(xr[half][f], W[f*HID + k], s);
        if (t < 64) g_vecA[node*HID + k] = s;
        else        g_vecB[node*HID + k] = s;
    } else {
        __shared__ float er[4][EF];
        int b   = blockIdx.x - NODE_BLOCKS;
        int grp = threadIdx.x >> 6;
        int k   = threadIdx.x & 63;
        int e   = b * 4 + grp;
        if (k < EF) er[grp][k] = ea[e*EF + k];
        __syncthreads();
        float s = g_biasC[k];
        #pragma unroll
        for (int f = 0; f < EF; f++) s = fmaf(er[grp][f], g_WC[f*HID + k], s);
        g_Ce[(size_t)e*HID + k] = s;
    }
}

// ---------------- K3: warp-MMA pairwise MLP (1 node/block, 128 thr) ----------
// SMEM byte offsets
#define SM_A_HI   0          // 96 x 128B = 12288   (bf16 H0 hi, SW128)
#define SM_A_LO   12288      // 12288
#define SM_B_HI   24576      // 64 x 128B = 8192    (bf16 W2 hi, pre-swizzled)
#define SM_B_LO   32768      // 8192
#define SM_AU     40960      // 256
#define SM_B2     41216      // 256
#define SM_W3     41472      // 256
#define SM_EL     41728      // 96*8 = 768
#define SM_E0     42496      // 384
#define SM_E1     42880      // 384
#define SM_NM     43264      // 384
#define SM_ECNT   43648      // 16
#define SM_RED    43664      // 96*4*4 = 1536
#define SM_TOTAL  45248

__global__ void __launch_bounds__(128, 4)
pair_kernel(const int* __restrict__ edge_index,
            const float* __restrict__ b2, const float* __restrict__ W3,
            const float* __restrict__ b3,
            float* __restrict__ out)
{
    extern __shared__ char smc[];
    const uint32_t sbase = (uint32_t)__cvta_generic_to_shared(smc);
    float*     Au_s = (float*)(smc + SM_AU);
    float*     b2s  = (float*)(smc + SM_B2);
    float*     W3s  = (float*)(smc + SM_W3);
    long long* el   = (long long*)(smc + SM_EL);
    int*       e0s  = (int*)(smc + SM_E0);
    int*       e1s  = (int*)(smc + SM_E1);
    int*       nms  = (int*)(smc + SM_NM);
    int*       ecnt = (int*)(smc + SM_ECNT);
    float*     red  = (float*)(smc + SM_RED);   // [96][4]

    const int t   = threadIdx.x;          // 0..127
    const int wid = t >> 5;
    const int lid = t & 31;
    const int u   = blockIdx.x;
    const int g   = u / NPG;

    if (t == 0) ecnt[0] = 0;

    // copy pre-swizzled B tiles (W2 hi/lo), load Au/b2/W3
    {
        const uint4* bh = (const uint4*)g_Bhi;
        const uint4* bl = (const uint4*)g_Blo;
        uint4* dh = (uint4*)(smc + SM_B_HI);
        uint4* dl = (uint4*)(smc + SM_B_LO);
        #pragma unroll
        for (int i = t; i < 512; i += 128) { dh[i] = bh[i]; dl[i] = bl[i]; }
    }
    if (t < 64) {
        Au_s[t] = g_vecA[(size_t)u*HID + t];
        b2s[t]  = b2[t];
        W3s[t]  = W3[t];
    }
    __syncthreads();

    // gather this node's out-edges
    {
        const int* srcA = edge_index;
        const int* dstA = edge_index + EDGES;
        for (int e = g*EPG + t; e < (g+1)*EPG; e += 128) {
            if (srcA[e] == u) {
                int p = atomicAdd(ecnt, 1);
                if (p < 96) el[p] = ((long long)e << 32) | (unsigned)(dstA[e] - g*NPG);
            }
        }
    }
    __syncthreads();
    const int ec = min(ecnt[0], 96);
    if (t == 0) {                       // deterministic order
        for (int a = 1; a < ec; a++) {
            long long v = el[a]; int b = a - 1;
            while (b >= 0 && el[b] > v) { el[b+1] = el[b]; b--; }
            el[b+1] = v;
        }
    }
    __syncthreads();
    if (t < 96) {                       // per-column (row j) match table
        int e0 = -1, e1 = -1, nm = 0;
        for (int q = 0; q < ec; q++) {
            long long pk = el[q];
            if ((int)(pk & 0xffffffffLL) == t) {
                int e = (int)(pk >> 32);
                if (nm == 0) e0 = e; else if (nm == 1) e1 = e;
                nm++;
            }
        }
        e0s[t] = e0; e1s[t] = e1; nms[t] = nm;
    }
    __syncthreads();

    // ---- build A tile: H0[j][m] = relu(vecB[j][m] + Au[m] + Ce) bf16 hi/lo --
    // 16 lanes per row, 8 rows per pass, 12 passes; coalesced LDG.128,
    // SW128-swizzled STS.64 (conflict-free).
    {
        const int rip = t >> 4;                 // row-in-pass 0..7
        const int l   = t & 15;                 // lane's 4 m-values
        const float4* au4 = (const float4*)Au_s;
        for (int pass = 0; pass < 12; pass++) {
            const int j = pass*8 + rip;
            float4 v = *(const float4*)(g_vecB + (size_t)(g*NPG + j)*HID + l*4);
            float4 a = au4[l];
            v.x += a.x; v.y += a.y; v.z += a.z; v.w += a.w;
            const int nm = nms[j];
            if (nm > 0) {
                float4 c = ((const float4*)(g_Ce + (size_t)e0s[j]*HID))[l];
                v.x += c.x; v.y += c.y; v.z += c.z; v.w += c.w;
                if (nm >= 2) {
                    c = ((const float4*)(g_Ce + (size_t)e1s[j]*HID))[l];
                    v.x += c.x; v.y += c.y; v.z += c.z; v.w += c.w;
                }
                if (nm > 2) {
                    int seen = 0;
                    for (int q = 0; q < ec; q++) {
                        long long pk = el[q];
                        if ((int)(pk & 0xffffffffLL) == j) {
                            seen++;
                            if (seen > 2) {
                                int e = (int)(pk >> 32);
                                c = ((const float4*)(g_Ce + (size_t)e*HID))[l];
                                v.x += c.x; v.y += c.y; v.z += c.z; v.w += c.w;
                            }
                        }
                    }
                }
            }
            v.x = fmaxf(v.x, 0.f); v.y = fmaxf(v.y, 0.f);
            v.z = fmaxf(v.z, 0.f); v.w = fmaxf(v.w, 0.f);
            uint32_t hi01 = pack_bf16x2(v.x, v.y);
            uint32_t hi23 = pack_bf16x2(v.z, v.w);
            float hx = __uint_as_float(hi01 << 16);
            float hy = __uint_as_float(hi01 & 0xFFFF0000u);
            float hz = __uint_as_float(hi23 << 16);
            float hw = __uint_as_float(hi23 & 0xFFFF0000u);
            uint32_t lo01 = pack_bf16x2(v.x - hx, v.y - hy);
            uint32_t lo23 = pack_bf16x2(v.z - hz, v.w - hw);
            uint32_t sw = sw128((uint32_t)j*128u + (uint32_t)l*8u);
            *(uint2*)(smc + SM_A_HI + sw) = make_uint2(hi01, hi23);
            *(uint2*)(smc + SM_A_LO + sw) = make_uint2(lo01, lo23);
        }
    }
    __syncthreads();

    // ---- warp-MMA GEMM: C[96,64] = A @ B; warp owns n-tiles {2w, 2w+1} ----
    // Preload B fragments (k16n8) via ldmatrix.x2.trans from row-major B[m][k].
    uint32_t Bh[2][4][2], Bl[2][4][2];
    #pragma unroll
    for (int nt2 = 0; nt2 < 2; nt2++) {
        const int nt = 2*wid + nt2;
        #pragma unroll
        for (int ks = 0; ks < 4; ks++) {
            uint32_t off = (uint32_t)(ks*16 + (lid & 15))*128u + (uint32_t)nt*16u;
            uint32_t sw  = sw128(off);
            ldsm_x2t(Bh[nt2][ks], sbase + SM_B_HI + sw);
            ldsm_x2t(Bl[nt2][ks], sbase + SM_B_LO + sw);
        }
    }

    float acc[6][2][4];
    #pragma unroll
    for (int mt = 0; mt < 6; mt++)
        #pragma unroll
        for (int n2 = 0; n2 < 2; n2++)
            #pragma unroll
            for (int q = 0; q < 4; q++) acc[mt][n2][q] = 0.f;

    #pragma unroll
    for (int mt = 0; mt < 6; mt++) {
        #pragma unroll
        for (int ks = 0; ks < 4; ks++) {
            uint32_t off = (uint32_t)(mt*16 + (lid & 15))*128u
                         + (uint32_t)ks*32u + (uint32_t)(lid >> 4)*16u;
            uint32_t sw  = sw128(off);
            uint32_t Ah[4], Al[4];
            ldsm_x4(Ah, sbase + SM_A_HI + sw);
            ldsm_x4(Al, sbase + SM_A_LO + sw);
            #pragma unroll
            for (int nt2 = 0; nt2 < 2; nt2++) {
                mma16816(acc[mt][nt2], Ah, Bh[nt2][ks]);
                mma16816(acc[mt][nt2], Ah, Bl[nt2][ks]);
                mma16816(acc[mt][nt2], Al, Bh[nt2][ks]);
            }
        }
    }

    // ---- epilogue: relu(h1+b2)*W3 on fragments, quad-shfl, cross-warp smem --
    {
        const int g4 = lid >> 2;     // 0..7  (row within tile)
        const int tg = lid & 3;      // 0..3  (col pair)
        #pragma unroll
        for (int mt = 0; mt < 6; mt++) {
            float pg = 0.f, pg8 = 0.f;
            #pragma unroll
            for (int nt2 = 0; nt2 < 2; nt2++) {
                const int c0 = (2*wid + nt2)*8 + tg*2;
                const float* d = acc[mt][nt2];
                float w0 = W3s[c0], w1 = W3s[c0+1];
                float bb0 = b2s[c0], bb1 = b2s[c0+1];
                pg  = fmaf(fmaxf(d[0] + bb0, 0.f), w0, pg);
                pg  = fmaf(fmaxf(d[1] + bb1, 0.f), w1, pg);
                pg8 = fmaf(fmaxf(d[2] + bb0, 0.f), w0, pg8);
                pg8 = fmaf(fmaxf(d[3] + bb1, 0.f), w1, pg8);
            }
            pg  += __shfl_xor_sync(0xffffffffu, pg, 1, 4);
            pg  += __shfl_xor_sync(0xffffffffu, pg, 2, 4);
            pg8 += __shfl_xor_sync(0xffffffffu, pg8, 1, 4);
            pg8 += __shfl_xor_sync(0xffffffffu, pg8, 2, 4);
            if (tg == 0) {
                red[(mt*16 + g4)*4 + wid]     = pg;
                red[(mt*16 + g4 + 8)*4 + wid] = pg8;
            }
        }
    }
    __syncthreads();
    if (t < 96) {
        float sv = (red[t*4+0] + red[t*4+1]) + (red[t*4+2] + red[t*4+3]);
        out[(size_t)u*NPG + t] = sv + b3[0];
    }
}

// ---------------- launch -----------------------------------------------------
extern "C" void kernel_launch(void* const* d_in, const int* in_sizes, int n_in,
                              void* d_out, int out_size)
{
    const float* x          = (const float*)d_in[0];
    const float* edge_attr  = (const float*)d_in[1];
    const int*   edge_index = (const int*)  d_in[2];

    int w = 6;
    if (n_in >= 6 && in_sizes[5] != 1) w = 5;
    if (n_in == 19) w = 5;
    const float* W_atom = (const float*)d_in[w+0];
    const float* b_atom = (const float*)d_in[w+1];
    const float* W_bond = (const float*)d_in[w+2];
    const float* b_bond = (const float*)d_in[w+3];
    const float* W_node = (const float*)d_in[w+4];
    const float* b_node = (const float*)d_in[w+5];
    const float* W_edge = (const float*)d_in[w+6];
    const float* b_edge = (const float*)d_in[w+7];
    const float* W1     = (const float*)d_in[w+8];
    const float* b1     = (const float*)d_in[w+9];
    const float* W2     = (const float*)d_in[w+10];
    const float* b2     = (const float*)d_in[w+11];
    const float* W3     = (const float*)d_in[w+12];
    const float* b3     = (const float*)d_in[w+13];

    cudaFuncSetAttribute(pair_kernel, cudaFuncAttributeMaxDynamicSharedMemorySize, SM_TOTAL);

    const int P1 = INF*HID + EF*HID + 2*HID;            // 3200
    const int P2 = 2*INF*HID + EF*HID + HID;            // 5184
    prep1_kernel<<<(P1 + 255)/256, 256>>>(W_atom, b_atom, W_bond, b_bond,
                                          W_node, b_node, W_edge, b_edge);
    prep2_kernel<<<(P2 + 255)/256, 256>>>(W1, b1);
    prep3_kernel<<<16, 256>>>(W2);
    encode_kernel<<<NODE_BLOCKS + EDGE_BLOCKS, 256>>>(x, edge_attr);
    pair_kernel<<<NODES, 128, SM_TOTAL>>>(edge_index, b2, W3, b3, (float*)d_out);
}

// round 16
// speedup vs baseline: 2.0511x; 1.1485x over previous
#include <cuda_runtime.h>
#include <cuda_bf16.h>
#include <cstdint>

// Problem constants (fixed by the reference generator)
#define NGR   64
#define NPG   96
#define NODES (NGR*NPG)       // 6144
#define HID   64
#define INF   32
#define EF    16
#define DEG   8
#define EDGES (NODES*DEG)     // 49152
#define EPG   (NPG*DEG)       // 768

// ---------------- scratch (static device globals) ---------------------------
__device__ float g_M1[INF*HID];
__device__ float g_M2[EF*HID];
__device__ float g_bn[HID];
__device__ float g_be[HID];
__device__ float g_WA[INF*HID];
__device__ float g_WB[INF*HID];
__device__ float g_WC[EF*HID];
__device__ float g_biasA[HID];
__device__ float g_biasB[HID];
__device__ float g_biasC[HID];
__device__ float g_vecA[NODES*HID];
__device__ float g_vecB[NODES*HID];              // [node][m]  (m contiguous)
__device__ float g_Ce[(size_t)EDGES*HID];
// W2 as bf16 hi/lo, 64 rows(m) x 64 cols(k), 128B rows, SW128-swizzled image
__device__ unsigned short g_Bhi[64*64];
__device__ unsigned short g_Blo[64*64];

// ---------------- warp-MMA helpers (base-target PTX, sm_80+) ----------------
__device__ __forceinline__ void ldsm_x4(uint32_t* r, uint32_t addr) {
    asm volatile("ldmatrix.sync.aligned.m8n8.x4.shared.b16 {%0,%1,%2,%3}, [%4];"
                 : "=r"(r[0]), "=r"(r[1]), "=r"(r[2]), "=r"(r[3]) : "r"(addr));
}
__device__ __forceinline__ void ldsm_x2t(uint32_t* r, uint32_t addr) {
    asm volatile("ldmatrix.sync.aligned.m8n8.x2.trans.shared.b16 {%0,%1}, [%2];"
                 : "=r"(r[0]), "=r"(r[1]) : "r"(addr));
}
__device__ __forceinline__ void mma16816(float* d, const uint32_t* a, const uint32_t* b) {
    asm volatile(
        "mma.sync.aligned.m16n8k16.row.col.f32.bf16.bf16.f32 "
        "{%0,%1,%2,%3}, {%4,%5,%6,%7}, {%8,%9}, {%0,%1,%2,%3};"
        : "+f"(d[0]), "+f"(d[1]), "+f"(d[2]), "+f"(d[3])
        : "r"(a[0]), "r"(a[1]), "r"(a[2]), "r"(a[3]), "r"(b[0]), "r"(b[1]));
}
__device__ __forceinline__ uint32_t pack_bf16x2(float lo_elem, float hi_elem) {
    uint32_t r;
    asm("cvt.rn.satfinite.bf16x2.f32 %0, %1, %2;" : "=r"(r) : "f"(hi_elem), "f"(lo_elem));
    return r;
}
__device__ __forceinline__ uint32_t sw128(uint32_t off) {
    return off ^ ((off >> 3) & 0x70u);
}

// ---------------- K1a (+ absorbed W2 split prep) -----------------------------
#define P1N (INF*HID + EF*HID + 2*HID)     // 3200
__global__ void prep1_kernel(const float* __restrict__ W_atom, const float* __restrict__ b_atom,
                             const float* __restrict__ W_bond, const float* __restrict__ b_bond,
                             const float* __restrict__ W_node, const float* __restrict__ b_node,
                             const float* __restrict__ W_edge, const float* __restrict__ b_edge,
                             const float* __restrict__ W2)
{
    int i = blockIdx.x * blockDim.x + threadIdx.x;
    if (i < INF*HID) {
        int r = i >> 6, k = i & 63;
        float s = 0.f;
        #pragma unroll 8
        for (int j = 0; j < HID; j++) s = fmaf(W_atom[r*HID+j], W_node[j*HID+k], s);
        g_M1[i] = s;
    } else if (i < INF*HID + EF*HID) {
        int i2 = i - INF*HID;
        int r = i2 >> 6, k = i2 & 63;
        float s = 0.f;
        #pragma unroll 8
        for (int j = 0; j < HID; j++) s = fmaf(W_bond[r*HID+j], W_edge[j*HID+k], s);
        g_M2[i2] = s;
    } else if (i < INF*HID + EF*HID + HID) {
        int k = i - (INF*HID + EF*HID);
        float s = b_node[k];
        #pragma unroll 8
        for (int j = 0; j < HID; j++) s = fmaf(b_atom[j], W_node[j*HID+k], s);
        g_bn[k] = s;
    } else if (i < P1N) {
        int k = i - (INF*HID + EF*HID + HID);
        float s = b_edge[k];
        #pragma unroll 8
        for (int j = 0; j < HID; j++) s = fmaf(b_bond[j], W_edge[j*HID+k], s);
        g_be[k] = s;
    } else if (i < P1N + 64*64) {
        // W2 -> swizzled bf16 hi/lo image (independent of the above)
        int i2 = i - P1N;
        int m = i2 >> 6, k = i2 & 63;
        float v = W2[m*HID + k];
        uint32_t b  = __float_as_uint(v);
        uint32_t hb = (b + 0x7FFFu + ((b >> 16) & 1u)) & 0xFFFF0000u;
        float hf = __uint_as_float(hb);
        float l  = v - hf;
        uint32_t lb32 = __float_as_uint(l);
        uint32_t lb   = (lb32 + 0x7FFFu + ((lb32 >> 16) & 1u)) & 0xFFFF0000u;
        uint32_t off = (uint32_t)m*128u + (uint32_t)k*2u;
        uint32_t sw  = sw128(off);
        g_Bhi[sw >> 1] = (unsigned short)(hb >> 16);
        g_Blo[sw >> 1] = (unsigned short)(lb >> 16);
    }
}

// ---------------- K1b ---------------------------------------------------------
__global__ void prep2_kernel(const float* __restrict__ W1, const float* __restrict__ b1)
{
    int i = blockIdx.x * blockDim.x + threadIdx.x;
    if (i < INF*HID) {
        int r = i >> 6, k = i & 63;
        float s = 0.f;
        #pragma unroll 8
        for (int j = 0; j < HID; j++) s = fmaf(g_M1[r*HID+j], W1[j*HID + k], s);
        g_WA[i] = s;
    } else if (i < 2*INF*HID) {
        int i2 = i - INF*HID;
        int r = i2 >> 6, k = i2 & 63;
        float s = 0.f;
        #pragma unroll 8
        for (int j = 0; j < HID; j++) s = fmaf(g_M1[r*HID+j], W1[(64+j)*HID + k], s);
        g_WB[i2] = s;
    } else if (i < 2*INF*HID + EF*HID) {
        int i2 = i - 2*INF*HID;
        int r = i2 >> 6, k = i2 & 63;
        float s = 0.f;
        #pragma unroll 8
        for (int j = 0; j < HID; j++) s = fmaf(g_M2[r*HID+j], W1[(128+j)*HID + k], s);
        g_WC[i2] = s;
    } else if (i < 2*INF*HID + EF*HID + HID) {
        int k = i - (2*INF*HID + EF*HID);
        float sa = b1[k], sb = 0.f, sc = 0.f;
        #pragma unroll 4
        for (int j = 0; j < HID; j++) {
            sa = fmaf(g_bn[j], W1[j*HID + k], sa);
            sb = fmaf(g_bn[j], W1[(64+j)*HID + k], sb);
            sc = fmaf(g_be[j], W1[(128+j)*HID + k], sc);
        }
        g_biasA[k] = sa;
        g_biasB[k] = sb;
        g_biasC[k] = sc;
    }
}

// ---------------- K2: batched per-node + per-edge layer-1 partials -----------
// node blocks: 4 nodes x 64 threads (each thread computes A and B dots)
// edge blocks: 16 edges, 4 groups x 64 threads, 4 edges per group
#define NODE_BLOCKS2 (NODES/4)     // 1536
#define EDGE_BLOCKS2 (EDGES/16)    // 3072
__global__ void encode_kernel(const float* __restrict__ x, const float* __restrict__ ea)
{
    if (blockIdx.x < NODE_BLOCKS2) {
        __shared__ float xr[4][INF];
        const int t  = threadIdx.x;
        const int ns = t >> 6;                 // node sub 0..3
        const int k  = t & 63;
        const int node = blockIdx.x*4 + ns;
        // coalesced feature load: 4*32 = 128 floats
        if (t < 4*INF) ((float*)xr)[t] = x[blockIdx.x*4*INF + t];
        __syncthreads();
        float sa = g_biasA[k], sb = g_biasB[k];
        #pragma unroll
        for (int f = 0; f < INF; f++) {
            float xv = xr[ns][f];
            sa = fmaf(xv, g_WA[f*HID + k], sa);
            sb = fmaf(xv, g_WB[f*HID + k], sb);
        }
        g_vecA[node*HID + k] = sa;
        g_vecB[node*HID + k] = sb;
    } else {
        __shared__ float er[16][EF];
        const int t   = threadIdx.x;
        const int grp = t >> 6;                // 0..3
        const int k   = t & 63;
        const int b   = blockIdx.x - NODE_BLOCKS2;
        const int e0  = b*16;
        // coalesced edge-attr load: 16*16 = 256 floats
        ((float*)er)[t] = ea[(size_t)e0*EF + t];
        __syncthreads();
        const float bc = g_biasC[k];
        float s0 = bc, s1 = bc, s2 = bc, s3 = bc;
        #pragma unroll
        for (int f = 0; f < EF; f++) {
            float wc = g_WC[f*HID + k];
            s0 = fmaf(er[grp*4+0][f], wc, s0);
            s1 = fmaf(er[grp*4+1][f], wc, s1);
            s2 = fmaf(er[grp*4+2][f], wc, s2);
            s3 = fmaf(er[grp*4+3][f], wc, s3);
        }
        g_Ce[(size_t)(e0 + grp*4 + 0)*HID + k] = s0;
        g_Ce[(size_t)(e0 + grp*4 + 1)*HID + k] = s1;
        g_Ce[(size_t)(e0 + grp*4 + 2)*HID + k] = s2;
        g_Ce[(size_t)(e0 + grp*4 + 3)*HID + k] = s3;
    }
}

// ---------------- K3: warp-MMA pairwise MLP (1 node/block, 128 thr) ----------
// SMEM byte offsets
#define SM_A_HI   0          // 96 x 128B = 12288   (bf16 H0 hi, SW128)
#define SM_A_LO   12288      // 12288
#define SM_B_HI   24576      // 64 x 128B = 8192    (bf16 W2 hi, pre-swizzled)
#define SM_B_LO   32768      // 8192
#define SM_AU     40960      // 256
#define SM_B2     41216      // 256
#define SM_W3     41472      // 256
#define SM_EL     41728      // 96*8 = 768
#define SM_E0     42496      // 384
#define SM_E1     42880      // 384
#define SM_NM     43264      // 384
#define SM_ECNT   43648      // 16
#define SM_RED    43664      // 96*4*4 = 1536
#define SM_TOTAL  45248

__global__ void __launch_bounds__(128, 4)
pair_kernel(const int* __restrict__ edge_index,
            const float* __restrict__ b2, const float* __restrict__ W3,
            const float* __restrict__ b3,
            float* __restrict__ out)
{
    extern __shared__ char smc[];
    const uint32_t sbase = (uint32_t)__cvta_generic_to_shared(smc);
    float*     Au_s = (float*)(smc + SM_AU);
    float*     b2s  = (float*)(smc + SM_B2);
    float*     W3s  = (float*)(smc + SM_W3);
    long long* el   = (long long*)(smc + SM_EL);
    int*       e0s  = (int*)(smc + SM_E0);
    int*       e1s  = (int*)(smc + SM_E1);
    int*       nms  = (int*)(smc + SM_NM);
    int*       ecnt = (int*)(smc + SM_ECNT);
    float*     red  = (float*)(smc + SM_RED);   // [96][4]

    const int t   = threadIdx.x;          // 0..127
    const int wid = t >> 5;
    const int lid = t & 31;
    const int u   = blockIdx.x;
    const int g   = u / NPG;

    if (t == 0) ecnt[0] = 0;

    // copy pre-swizzled B tiles (W2 hi/lo), load Au/b2/W3
    {
        const uint4* bh = (const uint4*)g_Bhi;
        const uint4* bl = (const uint4*)g_Blo;
        uint4* dh = (uint4*)(smc + SM_B_HI);
        uint4* dl = (uint4*)(smc + SM_B_LO);
        #pragma unroll
        for (int i = t; i < 512; i += 128) { dh[i] = bh[i]; dl[i] = bl[i]; }
    }
    if (t < 64) {
        Au_s[t] = g_vecA[(size_t)u*HID + t];
        b2s[t]  = b2[t];
        W3s[t]  = W3[t];
    }
    __syncthreads();

    // gather this node's out-edges
    {
        const int* srcA = edge_index;
        const int* dstA = edge_index + EDGES;
        for (int e = g*EPG + t; e < (g+1)*EPG; e += 128) {
            if (srcA[e] == u) {
                int p = atomicAdd(ecnt, 1);
                if (p < 96) el[p] = ((long long)e << 32) | (unsigned)(dstA[e] - g*NPG);
            }
        }
    }
    __syncthreads();
    const int ec = min(ecnt[0], 96);
    if (t == 0) {                       // deterministic order
        for (int a = 1; a < ec; a++) {
            long long v = el[a]; int b = a - 1;
            while (b >= 0 && el[b] > v) { el[b+1] = el[b]; b--; }
            el[b+1] = v;
        }
    }
    __syncthreads();
    if (t < 96) {                       // per-row match table
        int e0 = -1, e1 = -1, nm = 0;
        for (int q = 0; q < ec; q++) {
            long long pk = el[q];
            if ((int)(pk & 0xffffffffLL) == t) {
                int e = (int)(pk >> 32);
                if (nm == 0) e0 = e; else if (nm == 1) e1 = e;
                nm++;
            }
        }
        e0s[t] = e0; e1s[t] = e1; nms[t] = nm;
    }
    __syncthreads();

    // ---- build A tile with prefetch double-buffer ----
    // H0[j][m] = relu(vecB[j][m] + Au[m] + Ce) as bf16 hi/lo, SW128 STS.64.
    {
        const int rip = t >> 4;                 // row-in-pass 0..7
        const int l   = t & 15;                 // lane's 4 m-values
        const float4* au4 = (const float4*)Au_s;
        const float4 a = au4[l];
        float4 vnext = *(const float4*)(g_vecB + (size_t)(g*NPG + rip)*HID + l*4);
        for (int pass = 0; pass < 12; pass++) {
            const int j = pass*8 + rip;
            float4 v = vnext;
            if (pass < 11)
                vnext = *(const float4*)(g_vecB + (size_t)(g*NPG + j + 8)*HID + l*4);
            v.x += a.x; v.y += a.y; v.z += a.z; v.w += a.w;
            const int nm = nms[j];
            if (nm > 0) {
                float4 c = ((const float4*)(g_Ce + (size_t)e0s[j]*HID))[l];
                v.x += c.x; v.y += c.y; v.z += c.z; v.w += c.w;
                if (nm >= 2) {
                    c = ((const float4*)(g_Ce + (size_t)e1s[j]*HID))[l];
                    v.x += c.x; v.y += c.y; v.z += c.z; v.w += c.w;
                }
                if (nm > 2) {
                    int seen = 0;
                    for (int q = 0; q < ec; q++) {
                        long long pk = el[q];
                        if ((int)(pk & 0xffffffffLL) == j) {
                            seen++;
                            if (seen > 2) {
                                int e = (int)(pk >> 32);
                                c = ((const float4*)(g_Ce + (size_t)e*HID))[l];
                                v.x += c.x; v.y += c.y; v.z += c.z; v.w += c.w;
                            }
                        }
                    }
                }
            }
            v.x = fmaxf(v.x, 0.f); v.y = fmaxf(v.y, 0.f);
            v.z = fmaxf(v.z, 0.f); v.w = fmaxf(v.w, 0.f);
            uint32_t hi01 = pack_bf16x2(v.x, v.y);
            uint32_t hi23 = pack_bf16x2(v.z, v.w);
            float hx = __uint_as_float(hi01 << 16);
            float hy = __uint_as_float(hi01 & 0xFFFF0000u);
            float hz = __uint_as_float(hi23 << 16);
            float hw = __uint_as_float(hi23 & 0xFFFF0000u);
            uint32_t lo01 = pack_bf16x2(v.x - hx, v.y - hy);
            uint32_t lo23 = pack_bf16x2(v.z - hz, v.w - hw);
            uint32_t sw = sw128((uint32_t)j*128u + (uint32_t)l*8u);
            *(uint2*)(smc + SM_A_HI + sw) = make_uint2(hi01, hi23);
            *(uint2*)(smc + SM_A_LO + sw) = make_uint2(lo01, lo23);
        }
    }
    __syncthreads();

    // ---- warp-MMA GEMM: C[96,64] = A @ B; warp owns n-tiles {2w, 2w+1} ----
    uint32_t Bh[2][4][2], Bl[2][4][2];
    #pragma unroll
    for (int nt2 = 0; nt2 < 2; nt2++) {
        const int nt = 2*wid + nt2;
        #pragma unroll
        for (int ks = 0; ks < 4; ks++) {
            uint32_t off = (uint32_t)(ks*16 + (lid & 15))*128u + (uint32_t)nt*16u;
            uint32_t sw  = sw128(off);
            ldsm_x2t(Bh[nt2][ks], sbase + SM_B_HI + sw);
            ldsm_x2t(Bl[nt2][ks], sbase + SM_B_LO + sw);
        }
    }

    float acc[6][2][4];
    #pragma unroll
    for (int mt = 0; mt < 6; mt++)
        #pragma unroll
        for (int n2 = 0; n2 < 2; n2++)
            #pragma unroll
            for (int q = 0; q < 4; q++) acc[mt][n2][q] = 0.f;

    #pragma unroll
    for (int mt = 0; mt < 6; mt++) {
        #pragma unroll
        for (int ks = 0; ks < 4; ks++) {
            uint32_t off = (uint32_t)(mt*16 + (lid & 15))*128u
                         + (uint32_t)ks*32u + (uint32_t)(lid >> 4)*16u;
            uint32_t sw  = sw128(off);
            uint32_t Ah[4], Al[4];
            ldsm_x4(Ah, sbase + SM_A_HI + sw);
            ldsm_x4(Al, sbase + SM_A_LO + sw);
            #pragma unroll
            for (int nt2 = 0; nt2 < 2; nt2++) {
                mma16816(acc[mt][nt2], Ah, Bh[nt2][ks]);
                mma16816(acc[mt][nt2], Ah, Bl[nt2][ks]);
                mma16816(acc[mt][nt2], Al, Bh[nt2][ks]);
            }
        }
    }

    // ---- epilogue: relu(h1+b2)*W3 on fragments, quad-shfl, cross-warp smem --
    {
        const int g4 = lid >> 2;     // 0..7
        const int tg = lid & 3;      // 0..3
        #pragma unroll
        for (int mt = 0; mt < 6; mt++) {
            float pg = 0.f, pg8 = 0.f;
            #pragma unroll
            for (int nt2 = 0; nt2 < 2; nt2++) {
                const int c0 = (2*wid + nt2)*8 + tg*2;
                const float* d = acc[mt][nt2];
                float w0 = W3s[c0], w1 = W3s[c0+1];
                float bb0 = b2s[c0], bb1 = b2s[c0+1];
                pg  = fmaf(fmaxf(d[0] + bb0, 0.f), w0, pg);
                pg  = fmaf(fmaxf(d[1] + bb1, 0.f), w1, pg);
                pg8 = fmaf(fmaxf(d[2] + bb0, 0.f), w0, pg8);
                pg8 = fmaf(fmaxf(d[3] + bb1, 0.f), w1, pg8);
            }
            pg  += __shfl_xor_sync(0xffffffffu, pg, 1, 4);
            pg  += __shfl_xor_sync(0xffffffffu, pg, 2, 4);
            pg8 += __shfl_xor_sync(0xffffffffu, pg8, 1, 4);
            pg8 += __shfl_xor_sync(0xffffffffu, pg8, 2, 4);
            if (tg == 0) {
                red[(mt*16 + g4)*4 + wid]     = pg;
                red[(mt*16 + g4 + 8)*4 + wid] = pg8;
            }
        }
    }
    __syncthreads();
    if (t < 96) {
        float sv = (red[t*4+0] + red[t*4+1]) + (red[t*4+2] + red[t*4+3]);
        out[(size_t)u*NPG + t] = sv + b3[0];
    }
}

// ---------------- launch -----------------------------------------------------
extern "C" void kernel_launch(void* const* d_in, const int* in_sizes, int n_in,
                              void* d_out, int out_size)
{
    const float* x          = (const float*)d_in[0];
    const float* edge_attr  = (const float*)d_in[1];
    const int*   edge_index = (const int*)  d_in[2];

    int w = 6;
    if (n_in >= 6 && in_sizes[5] != 1) w = 5;
    if (n_in == 19) w = 5;
    const float* W_atom = (const float*)d_in[w+0];
    const float* b_atom = (const float*)d_in[w+1];
    const float* W_bond = (const float*)d_in[w+2];
    const float* b_bond = (const float*)d_in[w+3];
    const float* W_node = (const float*)d_in[w+4];
    const float* b_node = (const float*)d_in[w+5];
    const float* W_edge = (const float*)d_in[w+6];
    const float* b_edge = (const float*)d_in[w+7];
    const float* W1     = (const float*)d_in[w+8];
    const float* b1     = (const float*)d_in[w+9];
    const float* W2     = (const float*)d_in[w+10];
    const float* b2     = (const float*)d_in[w+11];
    const float* W3     = (const float*)d_in[w+12];
    const float* b3     = (const float*)d_in[w+13];

    cudaFuncSetAttribute(pair_kernel, cudaFuncAttributeMaxDynamicSharedMemorySize, SM_TOTAL);

    const int P1 = P1N + 64*64;                          // 3200 + 4096
    const int P2 = 2*INF*HID + EF*HID + HID;             // 5184
    prep1_kernel<<<(P1 + 255)/256, 256>>>(W_atom, b_atom, W_bond, b_bond,
                                          W_node, b_node, W_edge, b_edge, W2);
    prep2_kernel<<<(P2 + 255)/256, 256>>>(W1, b1);
    encode_kernel<<<NODE_BLOCKS2 + EDGE_BLOCKS2, 256>>>(x, edge_attr);
    pair_kernel<<<NODES, 128, SM_TOTAL>>>(edge_index, b2, W3, b3, (float*)d_out);
}